// round 13
// baseline (speedup 1.0000x reference)
#include <cuda_runtime.h>

#define Bdim 8
#define Ndim 8
#define Tdim 262144
#define ROWS (Bdim * Ndim)            // 64
#define CHUNKS 16                     // chunks per eIF row
#define EIF_BLOCKS (ROWS * CHUNKS)    // 1024
#define RECON_BLOCKS 256
#define WORKERS (EIF_BLOCKS + RECON_BLOCKS)   // 1280
#define GRID (WORKERS + 1)            // +1 manager block (bid 0)
#define THREADS 256
#define VEC_PER_CHUNK (Tdim / CHUNKS / 4)          // 4096 float4 per chunk
#define EIF_ITERS (VEC_PER_CHUNK / THREADS)        // 16
#define RECON_VEC (Bdim * Tdim / 4)                // 524288 float4 per array
#define RECON_ITERS (RECON_VEC / (RECON_BLOCKS * THREADS))  // 8

// All zero at module load. Manager block (bid 0) resets g_flag/g_done at the
// end of every run, so each kernel_launch (correctness, capture, replays)
// starts from the same state.
__device__ unsigned int g_flag;      // 1 = out[] zeroed + g_sscale published
__device__ unsigned int g_done;      // worker check-in counter
__device__ float        g_sscale;    // 1 / ((T-1) * count)

__device__ __forceinline__ void release_store(unsigned int* p, unsigned int v) {
    asm volatile("st.release.gpu.global.b32 [%0], %1;" :: "l"(p), "r"(v) : "memory");
}
__device__ __forceinline__ unsigned int acquire_load(const unsigned int* p) {
    unsigned int v;
    asm volatile("ld.acquire.gpu.global.b32 %0, [%1];" : "=r"(v) : "l"(p) : "memory");
    return v;
}
__device__ __forceinline__ void checkin_release() {
    asm volatile("red.release.gpu.global.add.u32 [%0], %1;"
                 :: "l"(&g_done), "r"(1u) : "memory");
}

__device__ __forceinline__ float block_reduce(float v, float* sm) {
    #pragma unroll
    for (int o = 16; o > 0; o >>= 1) v += __shfl_down_sync(0xffffffffu, v, o);
    int warp = threadIdx.x >> 5;
    __syncthreads();
    if ((threadIdx.x & 31) == 0) sm[warp] = v;
    __syncthreads();
    if (warp == 0) {
        v = (threadIdx.x < (THREADS >> 5)) ? sm[threadIdx.x] : 0.0f;
        #pragma unroll
        for (int o = 4; o > 0; o >>= 1) v += __shfl_down_sync(0xffffffffu, v, o);
    }
    return v;
}

__global__ void __launch_bounds__(THREADS, 6)
loss_onenode_kernel(const float* __restrict__ rr, const float* __restrict__ ri,
                    const float* __restrict__ tr, const float* __restrict__ ti,
                    const float* __restrict__ eIF, const float* __restrict__ tif,
                    const int* __restrict__ mode_mask, float* __restrict__ out)
{
    __shared__ float sm[THREADS / 32];
    const int tid = threadIdx.x;
    const int bid = blockIdx.x;

    if (bid == 0) {
        // ---- manager: count mask, publish scale, zero out, raise flag ----
        int mybit = (tid < ROWS) ? (mode_mask[tid] == 1) : 0;
        unsigned bal = __ballot_sync(0xffffffffu, mybit);
        __shared__ int cnt2[2];
        if ((tid >> 5) < 2 && (tid & 31) == 0) cnt2[tid >> 5] = __popc(bal);
        __syncthreads();
        if (tid == 0) {
            const float count = (float)(cnt2[0] + cnt2[1]);
            g_sscale = 1.0f / (262143.0f * fmaxf(count, 1.0f));
            out[0] = 0.0f; out[1] = 0.0f; out[2] = 0.0f; out[3] = 0.0f;
            release_store(&g_flag, 1u);          // publish: zeroed + scale ready

            // wait for all workers, then reset state for the next replay
            while (acquire_load(&g_done) != WORKERS) __nanosleep(128);
            g_flag = 0u;
            g_done = 0u;
        }
        return;
    }

    const int idx = bid - 1;            // worker index 0..1279

    if (idx < EIF_BLOCKS) {
        // ---- eIF / target_if path: one (row, chunk) per block ----
        const int row   = idx / CHUNKS;
        const int chunk = idx % CHUNKS;
        if (mode_mask[row] != 1) {      // masked: zero contribution, zero traffic
            if (tid == 0) checkin_release();
            return;
        }

        const size_t row_off = (size_t)row * Tdim;
        const float4* __restrict__ e4 = (const float4*)(eIF + row_off);
        const float4* __restrict__ t4 = (const float4*)(tif + row_off);
        const float*  __restrict__ er = eIF + row_off;

        const int vbase = chunk * VEC_PER_CHUNK;
        float acc_if = 0.0f, acc_sm = 0.0f;

        #pragma unroll 8
        for (int i = 0; i < EIF_ITERS; i++) {
            const int v = vbase + i * THREADS + tid;
            const float4 e  = e4[v];
            const float4 tf = t4[v];

            float dx = e.x - tf.x, dy = e.y - tf.y, dz = e.z - tf.z, dw = e.w - tf.w;
            acc_if += dx * dx + dy * dy + dz * dz + dw * dw;

            float d1 = e.y - e.x, d2 = e.z - e.y, d3 = e.w - e.z;
            acc_sm += d1 * d1 + d2 * d2 + d3 * d3;

            // neighbor e[t+4]: next lane's e.x, scalar patch at warp edge
            const int t = v * 4;
            float nx = __shfl_down_sync(0xffffffffu, e.x, 1);
            if ((tid & 31) == 31 && (t + 4 < Tdim)) nx = er[t + 4];
            if (t + 4 < Tdim) { float d4 = nx - e.w; acc_sm += d4 * d4; }
        }

        acc_if = block_reduce(acc_if, sm);
        acc_sm = block_reduce(acc_sm, sm);

        if (tid == 0) {
            // flag is set ~1us into the run; this block did >=3us of loads,
            // so the spin essentially never iterates.
            while (acquire_load(&g_flag) == 0u) __nanosleep(64);
            const float si = acc_if * (1.0f / 16777216.0f);   // / (B*N*T) = 2^-24
            const float ss = acc_sm * g_sscale;               // / ((T-1)*count)
            atomicAdd(out + 2, si);
            atomicAdd(out + 3, ss);
            atomicAdd(out + 0, 0.5f * si + 0.1f * ss);
            checkin_release();
        }
    } else {
        // ---- recon path: grid-stride over B*T with float4 ----
        const int rb = idx - EIF_BLOCKS;
        const float4* __restrict__ a = (const float4*)rr;
        const float4* __restrict__ b = (const float4*)ri;
        const float4* __restrict__ c = (const float4*)tr;
        const float4* __restrict__ d = (const float4*)ti;

        float acc = 0.0f;
        #pragma unroll
        for (int j = 0; j < RECON_ITERS; j++) {
            const int v = rb * THREADS + tid + j * (RECON_BLOCKS * THREADS);
            const float4 xr = a[v], xt = c[v];
            const float4 yr = b[v], yt = d[v];
            float d0 = xr.x - xt.x, d1 = xr.y - xt.y, d2 = xr.z - xt.z, d3 = xr.w - xt.w;
            acc += d0 * d0 + d1 * d1 + d2 * d2 + d3 * d3;
            float e0 = yr.x - yt.x, e1 = yr.y - yt.y, e2 = yr.z - yt.z, e3 = yr.w - yt.w;
            acc += e0 * e0 + e1 * e1 + e2 * e2 + e3 * e3;
        }
        acc = block_reduce(acc, sm);

        if (tid == 0) {
            while (acquire_load(&g_flag) == 0u) __nanosleep(64);
            const float sr = acc * (1.0f / 2097152.0f);       // / (B*T) = 2^-21
            atomicAdd(out + 1, sr);
            atomicAdd(out + 0, sr);
            checkin_release();
        }
    }
}

extern "C" void kernel_launch(void* const* d_in, const int* in_sizes, int n_in,
                              void* d_out, int out_size)
{
    const float* recon_real  = (const float*)d_in[0];
    const float* recon_imag  = (const float*)d_in[1];
    const float* target_real = (const float*)d_in[2];
    const float* target_imag = (const float*)d_in[3];
    const float* eIF         = (const float*)d_in[4];
    const float* target_if   = (const float*)d_in[5];
    const int*   mode_mask   = (const int*)d_in[6];
    float* out = (float*)d_out;

    loss_onenode_kernel<<<GRID, THREADS>>>(
        recon_real, recon_imag, target_real, target_imag, eIF, target_if,
        mode_mask, out);
}

// round 14
// speedup vs baseline: 1.1187x; 1.1187x over previous
#include <cuda_runtime.h>

#define Bdim 8
#define Ndim 8
#define Tdim 262144
#define ROWS (Bdim * Ndim)            // 64
#define CHUNKS 16                     // chunks per eIF row
#define EIF_BLOCKS (ROWS * CHUNKS)    // 1024
#define RECON_BLOCKS 256
#define THREADS 256
#define VEC_PER_CHUNK (Tdim / CHUNKS / 4)          // 4096 float4 per chunk
#define EIF_ITERS (VEC_PER_CHUNK / THREADS)        // 16
#define RECON_VEC (Bdim * Tdim / 4)                // 524288 float4 per array
#define RECON_ITERS (RECON_VEC / (RECON_BLOCKS * THREADS))  // 8

__device__ __forceinline__ float block_reduce(float v, float* sm) {
    #pragma unroll
    for (int o = 16; o > 0; o >>= 1) v += __shfl_down_sync(0xffffffffu, v, o);
    int warp = threadIdx.x >> 5;
    __syncthreads();
    if ((threadIdx.x & 31) == 0) sm[warp] = v;
    __syncthreads();
    if (warp == 0) {
        v = (threadIdx.x < (THREADS >> 5)) ? sm[threadIdx.x] : 0.0f;
        #pragma unroll
        for (int o = 4; o > 0; o >>= 1) v += __shfl_down_sync(0xffffffffu, v, o);
    }
    return v;
}

// out[] is zeroed by a memset NODE before this kernel (stream-ordered), so
// worker tails are pure atomics -- no waits, no fences, no flags, and no
// device-global state to reset (fully graph-replay safe).
__global__ void __launch_bounds__(THREADS, 6)
loss_main_kernel(const float* __restrict__ rr, const float* __restrict__ ri,
                 const float* __restrict__ tr, const float* __restrict__ ti,
                 const float* __restrict__ eIF, const float* __restrict__ tif,
                 const int* __restrict__ mode_mask, float* __restrict__ out)
{
    __shared__ float sm[THREADS / 32];
    __shared__ int cnt2[2];
    const int tid = threadIdx.x;
    const int bid = blockIdx.x;

    if (bid < EIF_BLOCKS) {
        // ---- eIF / target_if path: one (row, chunk) per block ----
        const int row   = bid / CHUNKS;
        const int chunk = bid % CHUNKS;
        if (mode_mask[row] != 1) return;   // masked row: zero contribution, zero traffic

        // mask count (for smooth scaling): 2-warp ballot, L2-hot mask
        int mybit = (tid < ROWS) ? (mode_mask[tid] == 1) : 0;
        unsigned bal = __ballot_sync(0xffffffffu, mybit);
        if ((tid >> 5) < 2 && (tid & 31) == 0) cnt2[tid >> 5] = __popc(bal);

        const size_t row_off = (size_t)row * Tdim;
        const float4* __restrict__ e4 = (const float4*)(eIF + row_off);
        const float4* __restrict__ t4 = (const float4*)(tif + row_off);
        const float*  __restrict__ er = eIF + row_off;

        const int vbase = chunk * VEC_PER_CHUNK;
        float acc_if = 0.0f, acc_sm = 0.0f;

        #pragma unroll 8
        for (int i = 0; i < EIF_ITERS; i++) {
            const int v = vbase + i * THREADS + tid;
            const float4 e  = e4[v];
            const float4 tf = t4[v];

            float dx = e.x - tf.x, dy = e.y - tf.y, dz = e.z - tf.z, dw = e.w - tf.w;
            acc_if += dx * dx + dy * dy + dz * dz + dw * dw;

            float d1 = e.y - e.x, d2 = e.z - e.y, d3 = e.w - e.z;
            acc_sm += d1 * d1 + d2 * d2 + d3 * d3;

            // neighbor e[t+4]: next lane's e.x, scalar patch at warp edge
            const int t = v * 4;
            float nx = __shfl_down_sync(0xffffffffu, e.x, 1);
            if ((tid & 31) == 31 && (t + 4 < Tdim)) nx = er[t + 4];
            if (t + 4 < Tdim) { float d4 = nx - e.w; acc_sm += d4 * d4; }
        }

        acc_if = block_reduce(acc_if, sm);   // internal syncthreads publish cnt2 too
        acc_sm = block_reduce(acc_sm, sm);

        if (tid == 0) {
            const float count = (float)(cnt2[0] + cnt2[1]);   // >0 (this row active)
            const float si = acc_if * (1.0f / 16777216.0f);   // / (B*N*T) = 2^-24, exact
            const float ss = acc_sm / (262143.0f * count);    // / ((T-1)*count)
            atomicAdd(out + 2, si);
            atomicAdd(out + 3, ss);
            atomicAdd(out + 0, 0.5f * si + 0.1f * ss);
        }
    } else {
        // ---- recon path: grid-stride over B*T with float4 ----
        const int rb = bid - EIF_BLOCKS;
        const float4* __restrict__ a = (const float4*)rr;
        const float4* __restrict__ b = (const float4*)ri;
        const float4* __restrict__ c = (const float4*)tr;
        const float4* __restrict__ d = (const float4*)ti;

        float acc = 0.0f;
        #pragma unroll
        for (int j = 0; j < RECON_ITERS; j++) {
            const int v = rb * THREADS + tid + j * (RECON_BLOCKS * THREADS);
            const float4 xr = a[v], xt = c[v];
            const float4 yr = b[v], yt = d[v];
            float d0 = xr.x - xt.x, d1 = xr.y - xt.y, d2 = xr.z - xt.z, d3 = xr.w - xt.w;
            acc += d0 * d0 + d1 * d1 + d2 * d2 + d3 * d3;
            float e0 = yr.x - yt.x, e1 = yr.y - yt.y, e2 = yr.z - yt.z, e3 = yr.w - yt.w;
            acc += e0 * e0 + e1 * e1 + e2 * e2 + e3 * e3;
        }
        acc = block_reduce(acc, sm);

        if (tid == 0) {
            const float sr = acc * (1.0f / 2097152.0f);       // / (B*T) = 2^-21, exact
            atomicAdd(out + 1, sr);
            atomicAdd(out + 0, sr);
        }
    }
}

extern "C" void kernel_launch(void* const* d_in, const int* in_sizes, int n_in,
                              void* d_out, int out_size)
{
    const float* recon_real  = (const float*)d_in[0];
    const float* recon_imag  = (const float*)d_in[1];
    const float* target_real = (const float*)d_in[2];
    const float* target_imag = (const float*)d_in[3];
    const float* eIF         = (const float*)d_in[4];
    const float* target_if   = (const float*)d_in[5];
    const int*   mode_mask   = (const int*)d_in[6];
    float* out = (float*)d_out;

    // Memset NODE (not a kernel) zeroes the 4 outputs; stream order makes it
    // complete before the main kernel's atomics. Async + capturable + no alloc.
    cudaMemsetAsync(d_out, 0, 4 * sizeof(float), 0);

    loss_main_kernel<<<EIF_BLOCKS + RECON_BLOCKS, THREADS>>>(
        recon_real, recon_imag, target_real, target_imag, eIF, target_if,
        mode_mask, out);
}